// round 16
// baseline (speedup 1.0000x reference)
#include <cuda_runtime.h>
#include <cstdint>

// Spike-latency encoder:
//   trace:  [B=1024, F=128] f32,  center: [C=8] f32
//   out:    [T=100, B=1024, N=F*C=1024] f32 one-hot along T per (b,n)
//
// out[t,b,f*8+c] = (bin(b,f,c) == t) ? 1.0f : 0.0f
//   bin = trunc( sel(2.5*|trace[b,f]-center[c]|) / 0.1 + 1 )
//   sel(x) = (x > 10.0f) ? 10.1f : x     (bin -> 102, never matches)
//
// 419 MB write stream at the ~6.2 TB/s DRAM write wall. R16 probes the
// last unsampled axis: CTA granularity. 128-thread blocks at 16 CTA/SM
// (same 2048 resident threads/SM as the R7 winner, but 2x independent
// CTA store bursts per SM scheduler to interleave against prologue
// latency). Grid 40960: each CTA covers half a b-row x one t-chunk.

#define BB 1024
#define FF 128
#define CC 8
#define NN 1024
#define TT 100
#define NCH 20          // t-chunks
#define TCH 5           // t-slabs per chunk

__global__ void __launch_bounds__(128, 16)
spike_latency_kernel(const float* __restrict__ trace,
                     const float* __restrict__ center,
                     float* __restrict__ out) {
    const int idx = blockIdx.x & (2 * BB - 1);   // (b, half) fast-varying
    const int tc  = blockIdx.x >> 11;            // 0..19  t-chunk
    const int b   = idx >> 1;                    // 0..1023
    const int h   = idx & 1;                     // half of the b-row
    const int tid = threadIdx.x;                 // 0..127
    const int n0  = (h << 9) + (tid << 2);       // 4 consecutive n
    const int f   = n0 >> 3;                     // all 4 n share one feature
    const int c0  = n0 & 7;                      // 0 or 4

    const float tv = __ldg(&trace[b * FF + f]);

    int bins[4];
#pragma unroll
    for (int j = 0; j < 4; j++) {
        float ct = __ldg(&center[c0 + j]);
        float tm = 2.5f * fabsf(tv - ct);          // SCALING * |diff|  (f32)
        if (tm > 10.0f) tm = 10.1f;                // cutoff -> TIME_LENGTH + DT
        // trunc(times/DT + 1), IEEE f32 divide (bit-match XLA div.rn:
        // one flipped bin alone would exceed the 1e-3 rel_err budget)
        bins[j] = (int)(__fdiv_rn(tm, 0.1f) + 1.0f);
    }

    const size_t stride4 = (size_t)BB * NN / 4;    // 262144 float4 per t-slab
    float4* outp = reinterpret_cast<float4*>(out + (size_t)b * NN + n0)
                 + (size_t)(tc * TCH) * stride4;

    const int tbase = tc * TCH;
#pragma unroll
    for (int i = 0; i < TCH; i++) {
        const int t = tbase + i;
        float4 v;
        v.x = (bins[0] == t) ? 1.0f : 0.0f;
        v.y = (bins[1] == t) ? 1.0f : 0.0f;
        v.z = (bins[2] == t) ? 1.0f : 0.0f;
        v.w = (bins[3] == t) ? 1.0f : 0.0f;
        __stcs(outp + (size_t)i * stride4, v);     // evict-first streaming store
    }
}

extern "C" void kernel_launch(void* const* d_in, const int* in_sizes, int n_in,
                              void* d_out, int out_size) {
    // Identify inputs by element count — robust to metadata ordering:
    //   trace: 131072 floats, center: 8 floats, dummies: 1 each
    const float* trace  = nullptr;
    const float* center = nullptr;
    for (int i = 0; i < n_in; i++) {
        if (in_sizes[i] == BB * FF)     trace  = (const float*)d_in[i];
        else if (in_sizes[i] == CC)     center = (const float*)d_in[i];
    }
    if (!trace)  trace  = (const float*)d_in[0];
    if (!center) center = (const float*)d_in[1];

    float* out = (float*)d_out;  // [100, 1024, 1024] f32 one-hot

    spike_latency_kernel<<<2 * BB * NCH, 128>>>(trace, center, out);
}

// round 17
// speedup vs baseline: 1.0059x; 1.0059x over previous
#include <cuda_runtime.h>
#include <cstdint>

// Spike-latency encoder (FINAL — converged configuration, R7 winner):
//   trace:  [B=1024, F=128] f32,  center: [C=8] f32
//   out:    [T=100, B=1024, N=F*C=1024] f32 one-hot along T per (b,n)
//
// out[t,b,f*8+c] = (bin(b,f,c) == t) ? 1.0f : 0.0f
//   bin = trunc( sel(2.5*|trace[b,f]-center[c]|) / 0.1 + 1 )
//   sel(x) = (x > 10.0f) ? 10.1f : x     (bin -> 102, never matches)
//
// 419 MB pure write stream at the measured ~6.2 TB/s DRAM write wall
// (hardware floor ~58us). Sixteen-round lever sweep, all axes closed:
// grid concurrency saturates ~20K CTAs; t-split optimum NCH=20; 8 CTA/SM;
// 128- vs 256-thread CTAs equivalent; STG.128 + __stcs optimal (v8,
// default-policy, evict_last all regress); b-fast CTA map; fused prologue
// (separate precompute pays launch overhead); persistent CTAs regress
// hard (the oversubscribed launch IS the store-MLP machine).

#define BB 1024
#define FF 128
#define CC 8
#define NN 1024
#define TT 100
#define NCH 20          // t-chunks
#define TCH 5           // t-slabs per chunk

__global__ void __launch_bounds__(256, 8)
spike_latency_kernel(const float* __restrict__ trace,
                     const float* __restrict__ center,
                     float* __restrict__ out) {
    const int b   = blockIdx.x & (BB - 1);   // 0..1023 (fast-varying)
    const int tc  = blockIdx.x >> 10;        // 0..19   t-chunk
    const int tid = threadIdx.x;             // 0..255
    const int n0  = tid << 2;                // 4 consecutive n per thread
    const int f   = n0 >> 3;                 // all 4 n share one feature
    const int c0  = n0 & 7;                  // 0 or 4

    const float tv = __ldg(&trace[b * FF + f]);

    int bins[4];
#pragma unroll
    for (int j = 0; j < 4; j++) {
        float ct = __ldg(&center[c0 + j]);
        float tm = 2.5f * fabsf(tv - ct);          // SCALING * |diff|  (f32)
        if (tm > 10.0f) tm = 10.1f;                // cutoff -> TIME_LENGTH + DT
        // trunc(times/DT + 1), IEEE f32 divide (bit-match XLA div.rn:
        // one flipped bin alone would exceed the 1e-3 rel_err budget)
        bins[j] = (int)(__fdiv_rn(tm, 0.1f) + 1.0f);
    }

    const size_t stride4 = (size_t)BB * NN / 4;    // 262144 float4 per t-slab
    float4* outp = reinterpret_cast<float4*>(out + (size_t)b * NN + n0)
                 + (size_t)(tc * TCH) * stride4;

    const int tbase = tc * TCH;
#pragma unroll
    for (int i = 0; i < TCH; i++) {
        const int t = tbase + i;
        float4 v;
        v.x = (bins[0] == t) ? 1.0f : 0.0f;
        v.y = (bins[1] == t) ? 1.0f : 0.0f;
        v.z = (bins[2] == t) ? 1.0f : 0.0f;
        v.w = (bins[3] == t) ? 1.0f : 0.0f;
        __stcs(outp + (size_t)i * stride4, v);     // evict-first streaming store
    }
}

extern "C" void kernel_launch(void* const* d_in, const int* in_sizes, int n_in,
                              void* d_out, int out_size) {
    // Identify inputs by element count — robust to metadata ordering:
    //   trace: 131072 floats, center: 8 floats, dummies: 1 each
    const float* trace  = nullptr;
    const float* center = nullptr;
    for (int i = 0; i < n_in; i++) {
        if (in_sizes[i] == BB * FF)     trace  = (const float*)d_in[i];
        else if (in_sizes[i] == CC)     center = (const float*)d_in[i];
    }
    if (!trace)  trace  = (const float*)d_in[0];
    if (!center) center = (const float*)d_in[1];

    float* out = (float*)d_out;  // [100, 1024, 1024] f32 one-hot

    spike_latency_kernel<<<BB * NCH, 256>>>(trace, center, out);
}